// round 10
// baseline (speedup 1.0000x reference)
#include <cuda_runtime.h>
#include <cuda_bf16.h>

#define NROWS  8192
#define DIM    1024
#define NPAIRS 1024
#define MARGIN_RANK 0.05f
#define FULL   0xFFFFFFFFu
#define K2_BLOCKS 8          // 128 buckets per block
#define CAP    2048          // smem slots per K2 block (range avg = 1024)

// ---------------- device scratch (no allocations allowed) ----------------
__device__ float g_sp[NROWS];     // dp * rsqrt(|row|^2)  (row order, no text norm)
__device__ float g_sn[NROWS];     // dn * rsqrt(|row|^2)
__device__ int   g_rank[NROWS];   // arrival rank within bucket (any permutation OK)
__device__ int   g_bcnt[NPAIRS];  // bucket counts (zeroed by K2 tail for replay)
__device__ float g_cons_sum, g_pos_sum, g_neg_sum;
__device__ int   g_cons_cnt, g_rank_cnt;
__device__ int   g_done;

// ---------------- K1: pure GEMV, 2 rows/warp, one wave --------------------
// 512 blocks x 256 threads = 4096 warps x 2 rows. Epilogue: lane 0 captures
// the row's bucket rank with one global atomic (contention ~8, fully parallel).
__global__ void __launch_bounds__(256) K1_gemv(
    const float4* __restrict__ x, const float4* __restrict__ tp4,
    const float4* __restrict__ tn4, const int* __restrict__ pair)
{
    int t = threadIdx.x, lane = t & 31, w = t >> 5;
    int rbase = (blockIdx.x * 8 + w) * 2;

    int p0 = 0, p1 = 0;
    if (lane == 0) { p0 = pair[rbase]; p1 = pair[rbase + 1]; }  // in flight early

    #pragma unroll
    for (int r = 0; r < 2; r++) {
        int row = rbase + r;
        const float4* r4 = x + (size_t)row * (DIM / 4);

        float4 v[8];
        #pragma unroll
        for (int k = 0; k < 8; k++) v[k] = r4[k * 32 + lane];   // 8 loads in flight

        float dp = 0.f, dn = 0.f, dx = 0.f;
        #pragma unroll
        for (int k = 0; k < 8; k++) {
            float4 p = __ldg(tp4 + k * 32 + lane);
            float4 q = __ldg(tn4 + k * 32 + lane);
            dp += v[k].x*p.x + v[k].y*p.y + v[k].z*p.z + v[k].w*p.w;
            dn += v[k].x*q.x + v[k].y*q.y + v[k].z*q.z + v[k].w*q.w;
            dx += v[k].x*v[k].x + v[k].y*v[k].y + v[k].z*v[k].z + v[k].w*v[k].w;
        }
        #pragma unroll
        for (int o = 16; o; o >>= 1) {
            dp += __shfl_xor_sync(FULL, dp, o);
            dn += __shfl_xor_sync(FULL, dn, o);
            dx += __shfl_xor_sync(FULL, dx, o);
        }
        if (lane == 0) {
            float inv = rsqrtf(dx);
            g_sp[row] = dp * inv;
            g_sn[row] = dn * inv;
            g_rank[row] = atomicAdd(&g_bcnt[r ? p1 : p0], 1);
        }
    }
}

// ---------------- K2: redundant scan + smem binning + all-pairs -----------
// 8 blocks x 1024 threads. Every block redundantly scans the 1024 counts
// (cheap, removes all inter-block ordering), then bins its own 128-bucket
// range into shared memory straight from pair/rank, then warps run the
// shuffle all-pairs loop. Last block finalizes and resets state for replay.
__global__ void __launch_bounds__(1024) K2_pairs(
    const float* __restrict__ tp, const float* __restrict__ tn,
    const int* __restrict__ pair, const int* __restrict__ lev,
    float* __restrict__ out)
{
    __shared__ int   scnt[NPAIRS];
    __shared__ int   sbs[NPAIRS + 1];
    __shared__ int   wtot[32];
    __shared__ float sA[32], sB[32];
    __shared__ float ssp[CAP], ssn[CAP];
    __shared__ int   slv[CAP];
    __shared__ float sinv[2];
    __shared__ int   slast;

    int t = threadIdx.x, lane = t & 31, w = t >> 5;

    // ---- text-vector inverse norms (redundant per block, L2-hot) ----
    float a = tp[t], b = tn[t];
    int   c = g_bcnt[t];            // issue count load early too
    float pa = a * a, pb = b * b;
    #pragma unroll
    for (int o = 16; o; o >>= 1) {
        pa += __shfl_xor_sync(FULL, pa, o);
        pb += __shfl_xor_sync(FULL, pb, o);
    }
    if (lane == 0) { sA[w] = pa; sB[w] = pb; }

    // ---- exclusive scan over 1024 counts ----
    int inc = c;
    #pragma unroll
    for (int o = 1; o < 32; o <<= 1) {
        int n = __shfl_up_sync(FULL, inc, o);
        if (lane >= o) inc += n;
    }
    if (lane == 31) wtot[w] = inc;
    __syncthreads();
    if (w == 0) {
        int v = wtot[lane], x = v;
        #pragma unroll
        for (int o = 1; o < 32; o <<= 1) {
            int n = __shfl_up_sync(FULL, x, o);
            if (lane >= o) x += n;
        }
        wtot[lane] = x - v;                    // exclusive warp offset
        float qa = sA[lane], qb = sB[lane];
        #pragma unroll
        for (int o = 16; o; o >>= 1) {
            qa += __shfl_xor_sync(FULL, qa, o);
            qb += __shfl_xor_sync(FULL, qb, o);
        }
        if (lane == 0) { sinv[0] = rsqrtf(qa); sinv[1] = rsqrtf(qb); }
    }
    __syncthreads();
    scnt[t] = c;
    sbs[t]  = wtot[w] + inc - c;               // exclusive start
    if (t == 0) { sbs[NPAIRS] = NROWS; slast = 0; }
    __syncthreads();

    int bk0     = blockIdx.x * 128;
    int base    = sbs[bk0];
    int n_range = sbs[bk0 + 128] - base;
    bool staged = (n_range <= CAP);
    float invp = sinv[0], invn = sinv[1];

    // ---- bin my 128 buckets' rows into shared memory ----
    if (staged) {
        for (int i = t; i < NROWS; i += 1024) {
            int p = pair[i];
            if ((p >> 7) == (int)blockIdx.x) {
                int slot = sbs[p] - base + g_rank[i];
                ssp[slot] = g_sp[i] * invp;
                ssn[slot] = g_sn[i] * invn;
                slv[slot] = lev[i];
            }
        }
    }
    __syncthreads();

    // ---- per-bucket all-pairs: warp w owns 4 buckets ----
    float cs = 0.f, ps = 0.f, ns = 0.f;
    int cc = 0, rc = 0;

    for (int q = 0; q < 4; q++) {
        int bk = bk0 + w * 4 + q;
        int bc = scnt[bk];
        int st = sbs[bk] - base;

        if (staged && bc <= 32) {
            float sp = 0.f, sn = 0.f; int lv = 0;
            bool act = lane < bc;
            if (act) { sp = ssp[st + lane]; sn = ssn[st + lane]; lv = slv[st + lane]; }
            for (int bi = 0; bi < bc; bi++) {
                float spb = __shfl_sync(FULL, sp, bi);
                float snb = __shfl_sync(FULL, sn, bi);
                int   lb  = __shfl_sync(FULL, lv, bi);
                if (act && lv == lb && lane < bi) {
                    cs += fabsf(sp - spb) + fabsf(sn - snb);
                    cc++;
                }
                if (act && lv < lb) {
                    ps += fmaxf(MARGIN_RANK - (sp - spb), 0.f);
                    ns += fmaxf(MARGIN_RANK + (sn - snb), 0.f);
                    rc++;
                }
            }
        } else if (staged) {
            // oversize bucket but staged range: iterate from shared
            for (int ai = lane; ai < bc; ai += 32) {
                float spa = ssp[st + ai], sna = ssn[st + ai];
                int   la  = slv[st + ai];
                for (int bi = 0; bi < bc; bi++) {
                    float spb = ssp[st + bi], snb = ssn[st + bi];
                    int   lb  = slv[st + bi];
                    if (la == lb && ai < bi) {
                        cs += fabsf(spa - spb) + fabsf(sna - snb);
                        cc++;
                    }
                    if (la < lb) {
                        ps += fmaxf(MARGIN_RANK - (spa - spb), 0.f);
                        ns += fmaxf(MARGIN_RANK + (sna - snb), 0.f);
                        rc++;
                    }
                }
            }
        } else {
            // astronomically-unlikely overflow: correct-but-slow global scan
            for (int ai = lane; ai < NROWS; ai += 32) {
                if (pair[ai] != bk) continue;
                int   ra  = g_rank[ai];
                float spa = g_sp[ai] * invp, sna = g_sn[ai] * invn;
                int   la  = lev[ai];
                for (int bi = 0; bi < NROWS; bi++) {
                    if (pair[bi] != bk) continue;
                    int   rb  = g_rank[bi];
                    float spb = g_sp[bi] * invp, snb = g_sn[bi] * invn;
                    int   lb  = lev[bi];
                    if (la == lb && ra < rb) {
                        cs += fabsf(spa - spb) + fabsf(sna - snb);
                        cc++;
                    }
                    if (la < lb) {
                        ps += fmaxf(MARGIN_RANK - (spa - spb), 0.f);
                        ns += fmaxf(MARGIN_RANK + (sna - snb), 0.f);
                        rc++;
                    }
                }
            }
        }
    }

    #pragma unroll
    for (int o = 16; o; o >>= 1) {
        cs += __shfl_xor_sync(FULL, cs, o);
        ps += __shfl_xor_sync(FULL, ps, o);
        ns += __shfl_xor_sync(FULL, ns, o);
        cc += __shfl_xor_sync(FULL, cc, o);
        rc += __shfl_xor_sync(FULL, rc, o);
    }
    if (lane == 0 && (cc | rc)) {
        atomicAdd(&g_cons_sum, cs);
        atomicAdd(&g_pos_sum,  ps);
        atomicAdd(&g_neg_sum,  ns);
        atomicAdd(&g_cons_cnt, cc);
        atomicAdd(&g_rank_cnt, rc);
    }

    // ---- finalize: last block writes scalar + resets state for replay ----
    __syncthreads();
    if (t == 0) {
        __threadfence();
        if (atomicAdd(&g_done, 1) == K2_BLOCKS - 1) slast = 1;
    }
    __syncthreads();
    if (slast) {
        g_bcnt[t] = 0;                       // all 1024 counters, one per thread
        if (t == 0) {
            __threadfence();
            float lc = (g_cons_cnt > 0) ? g_cons_sum / (float)(2 * g_cons_cnt) : 0.f;
            float lp = (g_rank_cnt > 0) ? g_pos_sum  / (float)g_rank_cnt       : 0.f;
            float ln = (g_rank_cnt > 0) ? g_neg_sum  / (float)g_rank_cnt       : 0.f;
            out[0] = lc + lp + ln;
            g_cons_sum = 0.f; g_pos_sum = 0.f; g_neg_sum = 0.f;
            g_cons_cnt = 0;   g_rank_cnt = 0;  g_done = 0;
        }
    }
}

// ---------------- launch ---------------------------------------------------
extern "C" void kernel_launch(void* const* d_in, const int* in_sizes, int n_in,
                              void* d_out, int out_size) {
    const float* img  = (const float*)d_in[0];  // [8192, 1024]
    const float* tp   = (const float*)d_in[1];  // [1024]
    const float* tn   = (const float*)d_in[2];  // [1024]
    const int*   lev  = (const int*)  d_in[3];  // [8192]
    const int*   pair = (const int*)  d_in[4];  // [8192]
    float* out = (float*)d_out;

    K1_gemv<<<NROWS / 16, 256>>>(
        (const float4*)img, (const float4*)tp, (const float4*)tn, pair);
    K2_pairs<<<K2_BLOCKS, 1024>>>(tp, tn, pair, lev, out);
}

// round 11
// speedup vs baseline: 1.2250x; 1.2250x over previous
#include <cuda_runtime.h>
#include <cuda_bf16.h>

#define NROWS  8192
#define DIM    1024
#define NPAIRS 1024
#define MARGIN_RANK 0.05f
#define FULL   0xFFFFFFFFu
#define K0_BLOCKS 8

// ---------------- device scratch (no allocations allowed) ----------------
__device__ int    g_rank[NROWS];      // arrival rank within bucket
__device__ int    g_bcnt[NPAIRS];     // bucket counts (zeroed by K2 for replay)
__device__ int    g_bstart[NPAIRS+1]; // exclusive starts + sentinel
__device__ float4 g_sorted[NROWS];    // {sim_pos, sim_neg, lev_bits, 0} bucket-sorted
__device__ float  g_invp, g_invn;     // text-vector inverse norms
__device__ float  g_cons_sum, g_pos_sum, g_neg_sum;
__device__ int    g_cons_cnt, g_rank_cnt;
__device__ int    g_arrive, g_done;   // completion counters (reset in-kernel)

// ---------------- K0: parallel ranks + norms + last-block scan ------------
// 8 blocks x 1024 threads, one row per thread. Ranks via global atomics
// (1024 counters, ~8-way contention). Block 0 computes text norms. The
// last block to finish runs the 1024-bucket exclusive scan.
__global__ void __launch_bounds__(1024) K0_prep(
    const float* __restrict__ tp, const float* __restrict__ tn,
    const int* __restrict__ pair)
{
    __shared__ float sA[32], sB[32];
    __shared__ int   wtot[32];
    __shared__ int   slast;

    int t = threadIdx.x, lane = t & 31, w = t >> 5;
    int i = blockIdx.x * 1024 + t;

    g_rank[i] = atomicAdd(&g_bcnt[pair[i]], 1);

    if (blockIdx.x == 0) {
        // text-vector inverse norms (t spans DIM exactly)
        float a = tp[t], b = tn[t];
        float pa = a * a, pb = b * b;
        #pragma unroll
        for (int o = 16; o; o >>= 1) {
            pa += __shfl_xor_sync(FULL, pa, o);
            pb += __shfl_xor_sync(FULL, pb, o);
        }
        if (lane == 0) { sA[w] = pa; sB[w] = pb; }
        __syncthreads();
        if (w == 0) {
            pa = sA[lane]; pb = sB[lane];
            #pragma unroll
            for (int o = 16; o; o >>= 1) {
                pa += __shfl_xor_sync(FULL, pa, o);
                pb += __shfl_xor_sync(FULL, pb, o);
            }
            if (lane == 0) { g_invp = rsqrtf(pa); g_invn = rsqrtf(pb); }
        }
        // zero accumulators for this launch
        if (t == 0) {
            g_cons_sum = 0.f; g_pos_sum = 0.f; g_neg_sum = 0.f;
            g_cons_cnt = 0;   g_rank_cnt = 0;  g_done = 0;
        }
    }

    // last-arriving block performs the scan (all counts final by then)
    __syncthreads();
    if (t == 0) {
        slast = 0;
        __threadfence();
        if (atomicAdd(&g_arrive, 1) == K0_BLOCKS - 1) slast = 1;
    }
    __syncthreads();
    if (slast) {
        __threadfence();                       // acquire all blocks' atomics
        int c = g_bcnt[t];
        int inc = c;
        #pragma unroll
        for (int o = 1; o < 32; o <<= 1) {
            int n = __shfl_up_sync(FULL, inc, o);
            if (lane >= o) inc += n;
        }
        if (lane == 31) wtot[w] = inc;
        __syncthreads();
        if (w == 0) {
            int v = wtot[lane], x = v;
            #pragma unroll
            for (int o = 1; o < 32; o <<= 1) {
                int n = __shfl_up_sync(FULL, x, o);
                if (lane >= o) x += n;
            }
            wtot[lane] = x - v;                // exclusive warp offset
        }
        __syncthreads();
        g_bstart[t] = wtot[w] + inc - c;       // exclusive start
        if (t == 0) { g_bstart[NPAIRS] = NROWS; g_arrive = 0; }
    }
}

// ---------------- K1: pure GEMV + fused direct scatter (R4-proven) --------
// 1024 blocks x 256 threads, one warp per row. Row loads issued first;
// lane 0 writes the finished record straight into bucket-sorted order.
__global__ void __launch_bounds__(256) K1_gemv(
    const float4* __restrict__ x, const float4* __restrict__ tp4,
    const float4* __restrict__ tn4, const int* __restrict__ pair,
    const int* __restrict__ lev)
{
    int t = threadIdx.x, lane = t & 31, w = t >> 5;
    int row = blockIdx.x * 8 + w;

    int p = 0, lv = 0;
    if (lane == 0) { p = pair[row]; lv = lev[row]; }   // in flight early

    const float4* r4 = x + (size_t)row * (DIM / 4);
    float4 v[8];
    #pragma unroll
    for (int k = 0; k < 8; k++) v[k] = r4[k * 32 + lane];   // 8 loads in flight

    float dp = 0.f, dn = 0.f, dx = 0.f;
    #pragma unroll
    for (int k = 0; k < 8; k++) {
        float4 pt = __ldg(tp4 + k * 32 + lane);
        float4 qt = __ldg(tn4 + k * 32 + lane);
        dp += v[k].x*pt.x + v[k].y*pt.y + v[k].z*pt.z + v[k].w*pt.w;
        dn += v[k].x*qt.x + v[k].y*qt.y + v[k].z*qt.z + v[k].w*qt.w;
        dx += v[k].x*v[k].x + v[k].y*v[k].y + v[k].z*v[k].z + v[k].w*v[k].w;
    }
    #pragma unroll
    for (int o = 16; o; o >>= 1) {
        dp += __shfl_xor_sync(FULL, dp, o);
        dn += __shfl_xor_sync(FULL, dn, o);
        dx += __shfl_xor_sync(FULL, dx, o);
    }
    if (lane == 0) {
        float inv = rsqrtf(dx);
        float4 o4;
        o4.x = dp * inv * g_invp;
        o4.y = dn * inv * g_invn;
        o4.z = __int_as_float(lv);
        o4.w = 0.f;
        g_sorted[g_bstart[p] + g_rank[row]] = o4;
    }
}

// ---------------- K2: warp-per-bucket shuffle all-pairs + finalize --------
// 128 blocks x 256 threads. Direct float4 read of the bucket (one load per
// lane), then pure shuffle all-pairs. Each block zeroes its 8 g_bcnt
// counters for the next graph replay; last block writes the scalar.
__global__ void __launch_bounds__(256) K2_pairs(float* __restrict__ out) {
    int t = threadIdx.x, lane = t & 31, w = t >> 5;
    int wg = blockIdx.x * 8 + w;

    if (t < 8) g_bcnt[blockIdx.x * 8 + t] = 0;     // replay reset

    int start = g_bstart[wg];
    int c     = g_bstart[wg + 1] - start;

    float cs = 0.f, ps = 0.f, ns = 0.f;
    int cc = 0, rc = 0;

    if (c <= 32) {
        float sp = 0.f, sn = 0.f; int lv = 0;
        bool act = lane < c;
        if (act) {
            float4 va = g_sorted[start + lane];
            sp = va.x; sn = va.y; lv = __float_as_int(va.z);
        }
        for (int b = 0; b < c; b++) {
            float spb = __shfl_sync(FULL, sp, b);
            float snb = __shfl_sync(FULL, sn, b);
            int   lb  = __shfl_sync(FULL, lv, b);
            if (act && lv == lb && lane < b) {
                cs += fabsf(sp - spb) + fabsf(sn - snb);
                cc++;
            }
            if (act && lv < lb) {
                ps += fmaxf(MARGIN_RANK - (sp - spb), 0.f);
                ns += fmaxf(MARGIN_RANK + (sn - snb), 0.f);
                rc++;
            }
        }
    } else {
        // fallback for improbable oversize buckets
        for (int a = lane; a < c; a += 32) {
            float4 va = g_sorted[start + a];
            int la = __float_as_int(va.z);
            for (int b = 0; b < c; b++) {
                float4 vb = g_sorted[start + b];
                int lb = __float_as_int(vb.z);
                if (la == lb && a < b) {
                    cs += fabsf(va.x - vb.x) + fabsf(va.y - vb.y);
                    cc++;
                }
                if (la < lb) {
                    ps += fmaxf(MARGIN_RANK - (va.x - vb.x), 0.f);
                    ns += fmaxf(MARGIN_RANK + (va.y - vb.y), 0.f);
                    rc++;
                }
            }
        }
    }

    #pragma unroll
    for (int o = 16; o; o >>= 1) {
        cs += __shfl_xor_sync(FULL, cs, o);
        ps += __shfl_xor_sync(FULL, ps, o);
        ns += __shfl_xor_sync(FULL, ns, o);
        cc += __shfl_xor_sync(FULL, cc, o);
        rc += __shfl_xor_sync(FULL, rc, o);
    }
    if (lane == 0 && (cc | rc)) {
        atomicAdd(&g_cons_sum, cs);
        atomicAdd(&g_pos_sum,  ps);
        atomicAdd(&g_neg_sum,  ns);
        atomicAdd(&g_cons_cnt, cc);
        atomicAdd(&g_rank_cnt, rc);
    }

    // fused finalize: last block writes the scalar + resets g_done
    __syncthreads();
    if (t == 0) {
        __threadfence();
        if (atomicAdd(&g_done, 1) == (int)gridDim.x - 1) {
            __threadfence();
            float lc = (g_cons_cnt > 0) ? g_cons_sum / (float)(2 * g_cons_cnt) : 0.f;
            float lp = (g_rank_cnt > 0) ? g_pos_sum  / (float)g_rank_cnt       : 0.f;
            float ln = (g_rank_cnt > 0) ? g_neg_sum  / (float)g_rank_cnt       : 0.f;
            out[0] = lc + lp + ln;
            g_done = 0;
        }
    }
}

// ---------------- launch ---------------------------------------------------
extern "C" void kernel_launch(void* const* d_in, const int* in_sizes, int n_in,
                              void* d_out, int out_size) {
    const float* img  = (const float*)d_in[0];  // [8192, 1024]
    const float* tp   = (const float*)d_in[1];  // [1024]
    const float* tn   = (const float*)d_in[2];  // [1024]
    const int*   lev  = (const int*)  d_in[3];  // [8192]
    const int*   pair = (const int*)  d_in[4];  // [8192]
    float* out = (float*)d_out;

    K0_prep<<<K0_BLOCKS, 1024>>>(tp, tn, pair);
    K1_gemv<<<NROWS / 8, 256>>>(
        (const float4*)img, (const float4*)tp, (const float4*)tn, pair, lev);
    K2_pairs<<<NPAIRS / 8, 256>>>(out);
}

// round 12
// speedup vs baseline: 1.2607x; 1.0291x over previous
#include <cuda_runtime.h>
#include <cuda_bf16.h>

#define NROWS  8192
#define DIM    1024
#define NPAIRS 1024
#define SLOTS  32            // fixed bin capacity; P(overflow) ~ 1e-8 (Poisson 8)
#define MARGIN_RANK 0.05f
#define FULL   0xFFFFFFFFu

// ---------------- device scratch (no allocations allowed) ----------------
__device__ float  g_sp[NROWS];             // row-order (overflow fallback only)
__device__ float  g_sn[NROWS];
__device__ int    g_bcnt[NPAIRS];          // counts; read+reset by K2 each launch
__device__ float4 g_slot[NPAIRS * SLOTS];  // direct-addressed bins {sp, sn, lev, 0}
__device__ float  g_invp, g_invn;          // text-vector inverse norms
__device__ float  g_cons_sum, g_pos_sum, g_neg_sum;
__device__ int    g_cons_cnt, g_rank_cnt;
__device__ int    g_done;

// ---------------- K1: GEMV + direct-bin scatter (no prep kernel) ----------
// Block 0: text inverse-norms. Blocks 1..1024: one warp per row.
// Lane 0 takes a rank with one global atomic and stores the finished record
// straight into its bucket's fixed 32-slot bin. No scan, no serial prelude.
__global__ void __launch_bounds__(256) K1_gemv(
    const float4* __restrict__ x, const float4* __restrict__ tp4,
    const float4* __restrict__ tn4, const int* __restrict__ pair,
    const int* __restrict__ lev)
{
    int t = threadIdx.x, lane = t & 31, w = t >> 5;

    if (blockIdx.x == 0) {
        __shared__ float sA[8], sB[8];
        const float* tp = (const float*)tp4;
        const float* tn = (const float*)tn4;
        float pa = 0.f, pb = 0.f;
        #pragma unroll
        for (int j = 0; j < 4; j++) {
            float a = tp[t + j * 256], b = tn[t + j * 256];
            pa += a * a;  pb += b * b;
        }
        #pragma unroll
        for (int o = 16; o; o >>= 1) {
            pa += __shfl_xor_sync(FULL, pa, o);
            pb += __shfl_xor_sync(FULL, pb, o);
        }
        if (lane == 0) { sA[w] = pa; sB[w] = pb; }
        __syncthreads();
        if (t == 0) {
            float qa = 0.f, qb = 0.f;
            #pragma unroll
            for (int j = 0; j < 8; j++) { qa += sA[j]; qb += sB[j]; }
            g_invp = rsqrtf(qa);
            g_invn = rsqrtf(qb);
        }
        return;
    }

    int row = (blockIdx.x - 1) * 8 + w;

    int p = 0, lv = 0;
    if (lane == 0) { p = pair[row]; lv = lev[row]; }   // in flight early

    const float4* r4 = x + (size_t)row * (DIM / 4);
    float4 v[8];
    #pragma unroll
    for (int k = 0; k < 8; k++) v[k] = r4[k * 32 + lane];   // 8 loads in flight

    float dp = 0.f, dn = 0.f, dx = 0.f;
    #pragma unroll
    for (int k = 0; k < 8; k++) {
        float4 pt = __ldg(tp4 + k * 32 + lane);
        float4 qt = __ldg(tn4 + k * 32 + lane);
        dp += v[k].x*pt.x + v[k].y*pt.y + v[k].z*pt.z + v[k].w*pt.w;
        dn += v[k].x*qt.x + v[k].y*qt.y + v[k].z*qt.z + v[k].w*qt.w;
        dx += v[k].x*v[k].x + v[k].y*v[k].y + v[k].z*v[k].z + v[k].w*v[k].w;
    }
    #pragma unroll
    for (int o = 16; o; o >>= 1) {
        dp += __shfl_xor_sync(FULL, dp, o);
        dn += __shfl_xor_sync(FULL, dn, o);
        dx += __shfl_xor_sync(FULL, dx, o);
    }
    if (lane == 0) {
        float inv = rsqrtf(dx);
        float sp = dp * inv, sn = dn * inv;     // raw (text norm applied in K2)
        g_sp[row] = sp;                          // overflow-fallback copy
        g_sn[row] = sn;
        int rank = atomicAdd(&g_bcnt[p], 1);
        if (rank < SLOTS) {
            float4 o4;
            o4.x = sp; o4.y = sn; o4.z = __int_as_float(lv); o4.w = 0.f;
            g_slot[p * SLOTS + rank] = o4;
        }
    }
}

// ---------------- K2: warp-per-bucket shuffle all-pairs + finalize --------
// 128 blocks x 256 threads. Lane 0 reads+resets its bucket count (replay
// safe); lanes read the bin coalesced (512B/warp), apply text norms, then
// pure shuffle all-pairs. Last block writes the scalar and resets state.
__global__ void __launch_bounds__(256) K2_pairs(
    const int* __restrict__ pair, const int* __restrict__ lev,
    float* __restrict__ out)
{
    int t = threadIdx.x, lane = t & 31, w = t >> 5;
    int wg = blockIdx.x * 8 + w;

    int c = 0;
    if (lane == 0) { c = g_bcnt[wg]; g_bcnt[wg] = 0; }   // read then reset
    c = __shfl_sync(FULL, c, 0);

    float invp = g_invp, invn = g_invn;

    float cs = 0.f, ps = 0.f, ns = 0.f;
    int cc = 0, rc = 0;

    if (c <= SLOTS) {
        float sp = 0.f, sn = 0.f; int lv = 0;
        bool act = lane < c;
        if (act) {
            float4 va = g_slot[wg * SLOTS + lane];       // coalesced 512B
            sp = va.x * invp; sn = va.y * invn; lv = __float_as_int(va.z);
        }
        for (int b = 0; b < c; b++) {
            float spb = __shfl_sync(FULL, sp, b);
            float snb = __shfl_sync(FULL, sn, b);
            int   lb  = __shfl_sync(FULL, lv, b);
            if (act && lv == lb && lane < b) {
                cs += fabsf(sp - spb) + fabsf(sn - snb);
                cc++;
            }
            if (act && lv < lb) {
                ps += fmaxf(MARGIN_RANK - (sp - spb), 0.f);
                ns += fmaxf(MARGIN_RANK + (sn - snb), 0.f);
                rc++;
            }
        }
    } else {
        // astronomically-unlikely overflow: correct-but-slow row scan
        for (int i = lane; i < NROWS; i += 32) {
            if (pair[i] != wg) continue;
            float spa = g_sp[i] * invp, sna = g_sn[i] * invn;
            int   la  = lev[i];
            for (int j = 0; j < NROWS; j++) {
                if (pair[j] != wg) continue;
                float spb = g_sp[j] * invp, snb = g_sn[j] * invn;
                int   lb  = lev[j];
                if (la == lb && i < j) {
                    cs += fabsf(spa - spb) + fabsf(sna - snb);
                    cc++;
                }
                if (la < lb) {
                    ps += fmaxf(MARGIN_RANK - (spa - spb), 0.f);
                    ns += fmaxf(MARGIN_RANK + (sna - snb), 0.f);
                    rc++;
                }
            }
        }
    }

    #pragma unroll
    for (int o = 16; o; o >>= 1) {
        cs += __shfl_xor_sync(FULL, cs, o);
        ps += __shfl_xor_sync(FULL, ps, o);
        ns += __shfl_xor_sync(FULL, ns, o);
        cc += __shfl_xor_sync(FULL, cc, o);
        rc += __shfl_xor_sync(FULL, rc, o);
    }
    if (lane == 0 && (cc | rc)) {
        atomicAdd(&g_cons_sum, cs);
        atomicAdd(&g_pos_sum,  ps);
        atomicAdd(&g_neg_sum,  ns);
        atomicAdd(&g_cons_cnt, cc);
        atomicAdd(&g_rank_cnt, rc);
    }

    // fused finalize: last block writes the scalar + resets state for replay
    __syncthreads();
    if (t == 0) {
        __threadfence();
        if (atomicAdd(&g_done, 1) == (int)gridDim.x - 1) {
            __threadfence();
            float lc = (g_cons_cnt > 0) ? g_cons_sum / (float)(2 * g_cons_cnt) : 0.f;
            float lp = (g_rank_cnt > 0) ? g_pos_sum  / (float)g_rank_cnt       : 0.f;
            float ln = (g_rank_cnt > 0) ? g_neg_sum  / (float)g_rank_cnt       : 0.f;
            out[0] = lc + lp + ln;
            g_cons_sum = 0.f; g_pos_sum = 0.f; g_neg_sum = 0.f;
            g_cons_cnt = 0;   g_rank_cnt = 0;  g_done = 0;
        }
    }
}

// ---------------- launch ---------------------------------------------------
extern "C" void kernel_launch(void* const* d_in, const int* in_sizes, int n_in,
                              void* d_out, int out_size) {
    const float* img  = (const float*)d_in[0];  // [8192, 1024]
    const float* tp   = (const float*)d_in[1];  // [1024]
    const float* tn   = (const float*)d_in[2];  // [1024]
    const int*   lev  = (const int*)  d_in[3];  // [8192]
    const int*   pair = (const int*)  d_in[4];  // [8192]
    float* out = (float*)d_out;

    K1_gemv<<<1 + NROWS / 8, 256>>>(
        (const float4*)img, (const float4*)tp, (const float4*)tn, pair, lev);
    K2_pairs<<<NPAIRS / 8, 256>>>(pair, lev, out);
}